// round 13
// baseline (speedup 1.0000x reference)
#include <cuda_runtime.h>
#include <cmath>
#include <stdint.h>

#define AMAX 1024
#define WORDS 32
#define BMAX 2
#define CMAX 80
#define NK 8           // compact neighbor-list capacity (per box)
#define RPB 13         // ceil(1024/80) adjacency rows per block
#define THREADS 512    // thread t owns boxes t and t+512 -> ~1 CTA per SM

// Scratch (static device arrays; no dynamic allocation allowed)
__device__ unsigned g_adjT[BMAX * WORDS * AMAX];          // 256 KB (fallback, degree>NK only)
__device__ unsigned short g_nbr[BMAX * AMAX * NK];        // 32 KB compact neighbor lists
__device__ int g_ncnt[BMAX * AMAX];                       // 8 KB degrees
__device__ int g_adone[BMAX];                             // monotone epoch counters

__device__ __forceinline__ float4 regress_box(const float* __restrict__ reg,
                                              const float4* __restrict__ anchors4,
                                              int b, int t, int A, float Wf, float Hf) {
    float4 av = anchors4[t];                       // one LDG.128
    float w = av.z - av.x, h = av.w - av.y;
    float cx = av.x + 0.5f * w, cy = av.y + 0.5f * h;
    const float* rb = reg + (size_t)b * 4 * A;
    float dx = rb[0 * A + t] * 0.1f;
    float dy = rb[1 * A + t] * 0.1f;
    float dw = rb[2 * A + t] * 0.2f;
    float dh = rb[3 * A + t] * 0.2f;
    float pcx = cx + dx * w, pcy = cy + dy * h;
    float pw = expf(dw) * w, ph = expf(dh) * h;
    float4 r;
    r.x = fmaxf(pcx - 0.5f * pw, 0.0f);
    r.y = fmaxf(pcy - 0.5f * ph, 0.0f);
    r.z = fminf(pcx + 0.5f * pw, Wf);
    r.w = fminf(pcy + 0.5f * ph, Hf);
    return r;
}

// Process one box in the async monotone dataflow. Returns true when decided.
__device__ __forceinline__ bool nms_step(int idx, float s, const unsigned short* js,
                                         int nh, bool ovf, const unsigned* adjT,
                                         const float* ssc,
                                         volatile unsigned char* sstate) {
    bool sup = false, alld = true;
    if (!ovf) {
        for (int k = 0; k < nh; ++k) {
            unsigned char v = sstate[js[k]];
            if (v == 2) { sup = true; break; }
            if (v == 0) alld = false;
        }
    } else {
        #pragma unroll
        for (int w = 0; w < WORDS; ++w) {
            unsigned mm = adjT[w * AMAX + idx];
            while (mm) {
                int bit = __ffs(mm) - 1; mm &= mm - 1;
                int j = w * 32 + bit;
                float sj = ssc[j];
                if (sj > s || (sj == s && j < idx)) {
                    unsigned char v = sstate[j];
                    if (v == 2) { sup = true; }
                    else if (v == 0) alld = false;
                }
            }
            if (sup) break;
        }
    }
    if (sup)  { sstate[idx] = 1; return true; }
    if (alld) { sstate[idx] = 2; return true; }
    return false;
}

// One fused kernel. Grid = B*C blocks x 512 threads, one (b,c) each.
// Thread t owns boxes t and t+512. ~1 CTA/SM: full SM issue/L1 per block.
__global__ void __launch_bounds__(THREADS, 2) fused_kernel(
    const float* __restrict__ cls, const float* __restrict__ reg,
    const float* __restrict__ anchors, float* __restrict__ out,
    int A, int C, int nBlocks, float Wf, float Hf) {
    __shared__ float4 sbox[AMAX];                   // 16 KB
    __shared__ float ssc[AMAX];                     // 4 KB
    __shared__ float sarea[AMAX];                   // 4 KB
    __shared__ unsigned sadj[RPB * 32];             // 1.7 KB ballot tile [row][word]
    __shared__ volatile unsigned char sstate[AMAX]; // 0=undec, 1=dropped, 2=kept
    int bid = blockIdx.x;
    int i = threadIdx.x;                            // 0..511
    int i2 = i + THREADS;                           // second owned box
    int lane = i & 31, wid = i >> 5;                // 16 warps
    int b = bid / C;
    int c = bid - b * C;
    int base = c * RPB;                             // first assigned adjacency row

    // Stage: regress both owned boxes + scores (reused everywhere).
    float s1 = cls[(size_t)bid * AMAX + i];
    float s2 = cls[(size_t)bid * AMAX + i2];
    float4 bx1 = regress_box(reg, (const float4*)anchors, b, i, A, Wf, Hf);
    float4 bx2 = regress_box(reg, (const float4*)anchors, b, i2, A, Wf, Hf);
    sbox[i] = bx1;  sbox[i2] = bx2;
    sarea[i]  = (bx1.z - bx1.x) * (bx1.w - bx1.y);  // same expr: bit-identical
    sarea[i2] = (bx2.z - bx2.x) * (bx2.w - bx2.y);
    ssc[i] = s1;  ssc[i2] = s2;
    sstate[i] = 0;  sstate[i2] = 0;
    __syncthreads();

    // ---- Phase 1a: warp wid owns column-words wid and wid+16, 13 rows ----
    {
        float4 bjA = sbox[wid * 32 + lane];         // column word wid
        float ajA = sarea[wid * 32 + lane];
        float4 bjB = sbox[(wid + 16) * 32 + lane];  // column word wid+16
        float ajB = sarea[(wid + 16) * 32 + lane];
        #pragma unroll
        for (int k = 0; k < RPB; ++k) {
            int row = base + k;
            if (row >= AMAX) break;
            float4 b0 = sbox[row];                  // broadcast LDS
            float a0 = sarea[row];
            float iA = fmaxf(fminf(b0.z, bjA.z) - fmaxf(b0.x, bjA.x), 0.0f) *
                       fmaxf(fminf(b0.w, bjA.w) - fmaxf(b0.y, bjA.y), 0.0f);
            float iB = fmaxf(fminf(b0.z, bjB.z) - fmaxf(b0.x, bjB.x), 0.0f) *
                       fmaxf(fminf(b0.w, bjB.w) - fmaxf(b0.y, bjB.y), 0.0f);
            // Conservative filter: IoU>0.5 => 3*inter > a+aj (real arithmetic);
            // 0.999 margin absorbs fp rounding. Exact decision via IEEE div
            // below -> bit-identical to reference.
            bool cA = 3.0f * iA >= 0.999f * (a0 + ajA);
            bool cB = 3.0f * iB >= 0.999f * (a0 + ajB);
            unsigned cb = __ballot_sync(0xffffffffu, cA || cB);
            unsigned balA = 0, balB = 0;
            if (cb) {                               // rare path (warp-uniform)
                bool adjA = cA && (__fdiv_rn(iA, fmaxf((a0 + ajA) - iA, 1e-9f)) > 0.5f);
                bool adjB = cB && (__fdiv_rn(iB, fmaxf((a0 + ajB) - iB, 1e-9f)) > 0.5f);
                balA = __ballot_sync(0xffffffffu, adjA);
                balB = __ballot_sync(0xffffffffu, adjB);
            }
            if (lane == 0) {
                sadj[k * 32 + wid] = balA;
                sadj[k * 32 + wid + 16] = balB;
            }
        }
    }
    __syncthreads();

    // ---- Phase 1b: warps 0..RPB-1 emit row (base+wid): lists + rare fallback ----
    if (wid < RPB && base + wid < AMAX) {
        int row = base + wid;
        unsigned m = sadj[wid * 32 + lane];
        if (lane == (row >> 5)) m &= ~(1u << (row & 31));    // drop self bit

        int cnt = __popc(m);
        int scan = cnt;
        #pragma unroll
        for (int d = 1; d < 32; d <<= 1) {
            int t = __shfl_up_sync(0xffffffffu, scan, d);
            if (lane >= d) scan += t;
        }
        int excl = scan - cnt;
        int tot = __shfl_sync(0xffffffffu, scan, 31);
        unsigned short* np = g_nbr + ((size_t)b * AMAX + row) * NK;
        unsigned mm = m;
        int pos = excl;
        while (mm && pos < NK) {
            int t2 = __ffs(mm) - 1; mm &= mm - 1;
            np[pos++] = (unsigned short)(lane * 32 + t2);
        }
        if (lane == 0) g_ncnt[b * AMAX + row] = tot;
        if (tot > NK)                                      // fallback rows only
            g_adjT[((size_t)b * WORDS + lane) * AMAX + row] = m;
    }
    __syncthreads();                  // all this block's rows written (CTA HB)

    // ---- Handoff: epoch counter (C increments/launch; monotone, replay-safe) ----
    if (i == 0) {
        __threadfence();              // release
        int v = atomicAdd(&g_adone[b], 1);
        int target = v - (v % C) + C;
        volatile int* dp = &g_adone[b];
        while (*dp < target) __nanosleep(64);
        __threadfence();              // acquire
    }
    __syncthreads();                  // adjacency for batch b visible

    // ---------------- Phase 2: async monotone-dataflow NMS (2 boxes/thread) ----------------
    const unsigned* adjT = g_adjT + (size_t)b * WORDS * AMAX;
    int tot1 = g_ncnt[b * AMAX + i];
    int tot2 = g_ncnt[b * AMAX + i2];
    uint4 nv1 = *(const uint4*)&g_nbr[((size_t)b * AMAX + i) * NK];
    uint4 nv2 = *(const uint4*)&g_nbr[((size_t)b * AMAX + i2) * NK];
    bool ovf1 = tot1 > NK, ovf2 = tot2 > NK;

    unsigned short js1[NK], js2[NK];
    int nh1 = 0, nh2 = 0;
    {
        unsigned w1[4] = {nv1.x, nv1.y, nv1.z, nv1.w};
        unsigned w2[4] = {nv2.x, nv2.y, nv2.z, nv2.w};
        int c1 = ovf1 ? 0 : tot1, c2 = ovf2 ? 0 : tot2;
        #pragma unroll
        for (int k = 0; k < NK; ++k) {
            if (k < c1) {
                int j = (w1[k >> 1] >> ((k & 1) * 16)) & 0xFFFF;
                float sj = ssc[j];
                if (sj > s1 || (sj == s1 && j < i)) js1[nh1++] = (unsigned short)j;
            }
            if (k < c2) {
                int j = (w2[k >> 1] >> ((k & 1) * 16)) & 0xFFFF;
                float sj = ssc[j];
                if (sj > s2 || (sj == s2 && j < i2)) js2[nh2++] = (unsigned short)j;
            }
        }
    }

    bool done1, done2;
    // Immediate decisions (keeps the dataflow seeds dense).
    if (!(s1 > 0.05f))        { sstate[i] = 1;  done1 = true; }
    else if (!ovf1 && nh1 == 0) { sstate[i] = 2;  done1 = true; }
    else done1 = false;
    if (!(s2 > 0.05f))        { sstate[i2] = 1; done2 = true; }
    else if (!ovf2 && nh2 == 0) { sstate[i2] = 2; done2 = true; }
    else done2 = false;

    // Spin both owned boxes in one loop; monotone bytes -> no fences needed.
    // Min-rank undecided box always has all higher nbrs decided -> progress.
    while (!(done1 && done2)) {
        if (!done1) done1 = nms_step(i,  s1, js1, nh1, ovf1, adjT, ssc, sstate);
        if (!done2) done2 = nms_step(i2, s2, js2, nh2, ovf2, adjT, ssc, sstate);
    }
    __syncthreads();                  // all decided; sstate stable

    // Coalesced float4 output: 5120 floats/block = 1280 float4 over 512 threads.
    const float* sboxf = (const float*)sbox;
    float4* obase4 = (float4*)(out + (size_t)bid * AMAX * 5);
    #pragma unroll
    for (int r = 0; r < 3; ++r) {
        int t = r * THREADS + i;
        if (t < (AMAX * 5) / 4) {
            float4 v;
            float* vf = (float*)&v;
            #pragma unroll
            for (int k = 0; k < 4; ++k) {
                int idx = t * 4 + k;
                int a = idx / 5;
                int f = idx - a * 5;
                float x = 0.0f;
                if (sstate[a] == 2) x = (f == 0) ? ssc[a] : sboxf[a * 4 + (f - 1)];
                vf[k] = x;
            }
            obase4[t] = v;
        }
    }
}

extern "C" void kernel_launch(void* const* d_in, const int* in_sizes, int n_in,
                              void* d_out, int out_size) {
    // metadata order: image, cls_pred, reg_pred, anchors
    const float* cls = (const float*)d_in[1];
    const float* reg = (const float*)d_in[2];
    const float* anchors = (const float*)d_in[3];

    int A = in_sizes[3] / 4;                 // 1024
    int B = in_sizes[2] / (4 * A);           // 2
    int C = in_sizes[1] / (B * A);           // 80
    long long hw = (long long)in_sizes[0] / (3LL * B);
    int H = (int)(sqrt((double)hw) + 0.5);   // 2048 (image used for shape only)
    float Hf = (float)H, Wf = (float)H;

    int nBlocks = B * C;                     // 160 blocks, ~1 per SM (148 SMs)
    fused_kernel<<<nBlocks, THREADS>>>(cls, reg, anchors, (float*)d_out,
                                       A, C, nBlocks, Wf, Hf);
}